// round 6
// baseline (speedup 1.0000x reference)
#include <cuda_runtime.h>
#include <math.h>

// Problem constants (fixed by the reference)
#define BNUM 64
#define NPER 1024
#define FDIM 128
#define ETOT (BNUM * NPER * 16)   // 1,048,576 edges
#define NT0  (BNUM * NPER)        // 65,536 nodes at layer 1
#define EPG0 16384                // edges per graph, layer 0 (contiguous)
#define ESTR1 16384               // per-graph edge bound after pool1 (HARD bound)
#define ESTR2 16384               // per-graph edge bound after pool2 (HARD bound)
#define CSLOT 64                  // CSR slots per node (in-degree ~Poisson(16))

typedef unsigned long long ull;

// ---------------- scratch (device globals; no runtime allocation) ----------
__device__ float g_P0[(size_t)NT0 * FDIM];      // xW buffer
__device__ float g_P1[(size_t)NT0 * FDIM];      // conv output
__device__ float g_deg[NT0];
__device__ int   g_cnt[NT0];
__device__ float g_score[NT0];
__device__ int   g_perm[NT0];
__device__ float g_vals[NT0];
__device__ int   g_es[ETOT];                    // layer-0 edges (converted)
__device__ int   g_ed[ETOT];
__device__ float g_ew[ETOT];
__device__ int   g_esA[BNUM * ESTR1];           // compacted edges after pool1
__device__ int   g_edA[BNUM * ESTR1];
__device__ float g_ewA[BNUM * ESTR1];
__device__ int   g_esB[BNUM * ESTR2];           // compacted edges after pool2
__device__ int   g_edB[BNUM * ESTR2];
__device__ float g_ewB[BNUM * ESTR2];
__device__ int   g_gecA[BNUM];                  // per-graph live-edge counts
__device__ int   g_gecB[BNUM];
__device__ int   g_csrc[(size_t)NT0 * CSLOT];   // fixed-stride CSR: src ids
__device__ float g_cnorm[(size_t)NT0 * CSLOT];  // fixed-stride CSR: norms
__device__ float g_pnorm[3];

__device__ __forceinline__ ull fma2(ull a, ull b, ull c) {
    ull d;
    asm("fma.rn.f32x2 %0, %1, %2, %3;" : "=l"(d) : "l"(a), "l"(b), "l"(c));
    return d;
}

// ---------------- ||p|| for the three pooling layers ------------------------
__global__ void k_pnorm3(const float* __restrict__ p1,
                         const float* __restrict__ p2,
                         const float* __restrict__ p3) {
    __shared__ float sh[FDIM];
    const float* p = (blockIdx.x == 0) ? p1 : (blockIdx.x == 1) ? p2 : p3;
    float v = p[threadIdx.x];
    sh[threadIdx.x] = v * v;
    __syncthreads();
    for (int s = 64; s > 0; s >>= 1) {
        if (threadIdx.x < s) sh[threadIdx.x] += sh[threadIdx.x + s];
        __syncthreads();
    }
    if (threadIdx.x == 0) g_pnorm[blockIdx.x] = sqrtf(sh[0]);
}

// ---------------- k_edges: block = graph -------------------------------------
// dtype probe + edge conversion + shared-mem degree + layer-1 CSR fill, fused.
__global__ void __launch_bounds__(1024) k_edges(const int* __restrict__ ei,
                                                const float* __restrict__ ew) {
    __shared__ float sdeg[NPER];
    __shared__ int   scnt[NPER];
    __shared__ int   s64;
    const int g = blockIdx.x, t = threadIdx.x;
    sdeg[t] = 0.f;
    scnt[t] = 0;
    if (t == 0) s64 = 1;
    __syncthreads();
    const int e0 = g * EPG0;
    // probe: for int64 edge ids (<2^31) all odd words are 0; for int32 they are
    // node ids (nonzero with overwhelming probability over 512 samples)
    if (t < 512 && ei[2 * (e0 + t) + 1] != 0) s64 = 0;
    __syncthreads();
    const int is64 = s64;
    int   ls[EPG0 / 1024], ld[EPG0 / 1024];
    float lw[EPG0 / 1024];
    #pragma unroll
    for (int j = 0; j < EPG0 / 1024; j++) {
        int e = e0 + t + j * 1024;
        int s, d;
        if (is64) { s = ei[2 * e]; d = ei[2 * (ETOT + e)]; }
        else      { s = ei[e];     d = ei[ETOT + e]; }
        float w = ew[e];
        ls[j] = s; ld[j] = d; lw[j] = w;
        g_es[e] = s; g_ed[e] = d; g_ew[e] = w;
        if (w != 0.f) atomicAdd(&sdeg[d - g * NPER], w);
    }
    __syncthreads();
    #pragma unroll
    for (int j = 0; j < EPG0 / 1024; j++) {
        float w = lw[j];
        if (w == 0.f) continue;
        int s = ls[j], d = ld[j];
        int sl = s - g * NPER, dl = d - g * NPER;
        float nv = rsqrtf(sdeg[sl] + 1.f) * w * rsqrtf(sdeg[dl] + 1.f);
        int pos = atomicAdd(&scnt[dl], 1);
        if (pos < CSLOT) {
            g_csrc[(size_t)d * CSLOT + pos] = s;
            g_cnorm[(size_t)d * CSLOT + pos] = nv;
        }
    }
    __syncthreads();
    g_deg[g * NPER + t] = sdeg[t];
    g_cnt[g * NPER + t] = min(scnt[t], CSLOT);
}

// ---------------- GEMM (f32x2 packed): Y[NT,128] = X[NT,128] @ W[128,128] ----
__global__ void __launch_bounds__(128) k_gemm2(const float* __restrict__ X,
                                               const float* __restrict__ W,
                                               float* __restrict__ Y) {
    __shared__ float2 xs2[32][FDIM];
    const int row0 = blockIdx.x * 32;
    const int tid = threadIdx.x;
    const int tx = tid & 63, ty = tid >> 6;
    #pragma unroll
    for (int i = tid; i < 32 * FDIM; i += 128) {
        int r = i >> 7, k = i & 127;
        float v = X[(row0 + r) * FDIM + k];
        xs2[r][k] = make_float2(v, v);
    }
    __syncthreads();
    const ull* W2 = (const ull*)W;
    ull acc[16];
    #pragma unroll
    for (int r = 0; r < 16; r++) acc[r] = 0ull;
    const ull* xrow = (const ull*)&xs2[ty * 16][0];
    #pragma unroll 4
    for (int k = 0; k < FDIM; k++) {
        ull w2 = W2[k * 64 + tx];
        #pragma unroll
        for (int r = 0; r < 16; r++)
            acc[r] = fma2(xrow[r * FDIM + k], w2, acc[r]);
    }
    float2* Y2 = (float2*)Y;
    #pragma unroll
    for (int r = 0; r < 16; r++) {
        float2 res = *(float2*)&acc[r];
        Y2[(row0 + ty * 16 + r) * 64 + tx] = res;
    }
}

// Same GEMM with fused pool-gather: row m = relu(H[g*n + perm[m]] * vals[m]).
__global__ void __launch_bounds__(128) k_gemm2_g(const float* __restrict__ H,
                                                 const float* __restrict__ W,
                                                 float* __restrict__ Y,
                                                 int n, int kshift) {
    __shared__ float2 xs2[32][FDIM];
    const int row0 = blockIdx.x * 32;
    const int tid = threadIdx.x;
    const int tx = tid & 63, ty = tid >> 6;
    #pragma unroll
    for (int i = tid; i < 32 * FDIM; i += 128) {
        int r = i >> 7, k = i & 127;
        int m = row0 + r;
        int g = m >> kshift;
        int row = g * n + g_perm[m];
        float v = fmaxf(H[row * FDIM + k] * g_vals[m], 0.f);
        xs2[r][k] = make_float2(v, v);
    }
    __syncthreads();
    const ull* W2 = (const ull*)W;
    ull acc[16];
    #pragma unroll
    for (int r = 0; r < 16; r++) acc[r] = 0ull;
    const ull* xrow = (const ull*)&xs2[ty * 16][0];
    #pragma unroll 4
    for (int k = 0; k < FDIM; k++) {
        ull w2 = W2[k * 64 + tx];
        #pragma unroll
        for (int r = 0; r < 16; r++)
            acc[r] = fma2(xrow[r * FDIM + k], w2, acc[r]);
    }
    float2* Y2 = (float2*)Y;
    #pragma unroll
    for (int r = 0; r < 16; r++) {
        float2 res = *(float2*)&acc[r];
        Y2[(row0 + ty * 16 + r) * 64 + tx] = res;
    }
}

// ---------------- aggregate + fused topk score: warp per dst node ------------
// MLP-4 unrolled gather: the node's CSR segment (<=64 records) is preloaded
// into 2 regs/lane; edges processed 4 at a time with 4 independent LDG.128
// and two accumulators (halved FMA dependency chain).
__global__ void __launch_bounds__(256) k_aggregate(const float* __restrict__ xW,
                                                   const float* __restrict__ b,
                                                   const float* __restrict__ p,
                                                   float* __restrict__ out,
                                                   int nt, int layer) {
    int node = blockIdx.x * 8 + (threadIdx.x >> 5);
    int lane = threadIdx.x & 31;
    if (node >= nt) return;
    const float4* xw4 = (const float4*)xW;
    float4 bv = ((const float4*)b)[lane];
    float di = rsqrtf(g_deg[node] + 1.f);
    float sl = di * di;
    float4 sv = xw4[(size_t)node * 32 + lane];
    float4 acc, acc2;
    acc.x = sl * sv.x + bv.x;
    acc.y = sl * sv.y + bv.y;
    acc.z = sl * sv.z + bv.z;
    acc.w = sl * sv.w + bv.w;
    acc2.x = 0.f; acc2.y = 0.f; acc2.z = 0.f; acc2.w = 0.f;
    const int cnt = g_cnt[node];
    const size_t base = (size_t)node * CSLOT;
    // preload CSR segment: records [0,32) -> (sA,nA), [32,64) -> (sB,nB)
    int sA = 0, sB = 0; float nA = 0.f, nB = 0.f;
    if (lane < cnt)      { sA = g_csrc[base + lane];      nA = g_cnorm[base + lane]; }
    if (32 + lane < cnt) { sB = g_csrc[base + 32 + lane]; nB = g_cnorm[base + 32 + lane]; }
    int j = 0;
    for (; j + 4 <= cnt; j += 4) {
        int t0 = ((j + 0) & 32) ? sB : sA;   // uniform select (j warp-uniform)
        int t1 = ((j + 1) & 32) ? sB : sA;
        int t2 = ((j + 2) & 32) ? sB : sA;
        int t3 = ((j + 3) & 32) ? sB : sA;
        float u0 = ((j + 0) & 32) ? nB : nA;
        float u1 = ((j + 1) & 32) ? nB : nA;
        float u2 = ((j + 2) & 32) ? nB : nA;
        float u3 = ((j + 3) & 32) ? nB : nA;
        int   s0 = __shfl_sync(0xffffffffu, t0, (j + 0) & 31);
        int   s1 = __shfl_sync(0xffffffffu, t1, (j + 1) & 31);
        int   s2 = __shfl_sync(0xffffffffu, t2, (j + 2) & 31);
        int   s3 = __shfl_sync(0xffffffffu, t3, (j + 3) & 31);
        float m0 = __shfl_sync(0xffffffffu, u0, (j + 0) & 31);
        float m1 = __shfl_sync(0xffffffffu, u1, (j + 1) & 31);
        float m2 = __shfl_sync(0xffffffffu, u2, (j + 2) & 31);
        float m3 = __shfl_sync(0xffffffffu, u3, (j + 3) & 31);
        float4 v0 = xw4[(size_t)s0 * 32 + lane];   // 4 independent LDG.128
        float4 v1 = xw4[(size_t)s1 * 32 + lane];
        float4 v2 = xw4[(size_t)s2 * 32 + lane];
        float4 v3 = xw4[(size_t)s3 * 32 + lane];
        acc.x  = fmaf(m0, v0.x, acc.x);  acc2.x = fmaf(m1, v1.x, acc2.x);
        acc.y  = fmaf(m0, v0.y, acc.y);  acc2.y = fmaf(m1, v1.y, acc2.y);
        acc.z  = fmaf(m0, v0.z, acc.z);  acc2.z = fmaf(m1, v1.z, acc2.z);
        acc.w  = fmaf(m0, v0.w, acc.w);  acc2.w = fmaf(m1, v1.w, acc2.w);
        acc.x  = fmaf(m2, v2.x, acc.x);  acc2.x = fmaf(m3, v3.x, acc2.x);
        acc.y  = fmaf(m2, v2.y, acc.y);  acc2.y = fmaf(m3, v3.y, acc2.y);
        acc.z  = fmaf(m2, v2.z, acc.z);  acc2.z = fmaf(m3, v3.z, acc2.z);
        acc.w  = fmaf(m2, v2.w, acc.w);  acc2.w = fmaf(m3, v3.w, acc2.w);
    }
    for (; j < cnt; j++) {
        int   tj = (j & 32) ? sB : sA;
        float uj = (j & 32) ? nB : nA;
        int   s  = __shfl_sync(0xffffffffu, tj, j & 31);
        float m  = __shfl_sync(0xffffffffu, uj, j & 31);
        float4 v = xw4[(size_t)s * 32 + lane];
        acc.x = fmaf(m, v.x, acc.x);
        acc.y = fmaf(m, v.y, acc.y);
        acc.z = fmaf(m, v.z, acc.z);
        acc.w = fmaf(m, v.w, acc.w);
    }
    acc.x += acc2.x; acc.y += acc2.y; acc.z += acc2.z; acc.w += acc2.w;
    ((float4*)out)[(size_t)node * 32 + lane] = acc;
    // fused topk score
    float4 pv = ((const float4*)p)[lane];
    float ds = acc.x * pv.x + acc.y * pv.y + acc.z * pv.z + acc.w * pv.w;
    #pragma unroll
    for (int o = 16; o > 0; o >>= 1) ds += __shfl_xor_sync(0xffffffffu, ds, o);
    if (lane == 0) {
        float sc = ds / g_pnorm[layer];
        g_score[node] = 1.f / (1.f + expf(-sc));
    }
}

// ---------------- topk + remap + compact + deg + CSR fill (block = graph) ----
__global__ void k_topk_rf(int n, int k,
                          const int* __restrict__ esi, const int* __restrict__ edi,
                          const float* __restrict__ ewi, int istride,
                          const int* __restrict__ gcin, int fixedc,
                          int* __restrict__ eso, int* __restrict__ edo,
                          float* __restrict__ ewo, int ostride,
                          int* __restrict__ gcout, int do_remap) {
    __shared__ ull   keys[1024];
    __shared__ int   inv[1024];
    __shared__ float sdeg[512];
    __shared__ int   scnt[512];
    __shared__ int   secnt;
    const int g = blockIdx.x, t = threadIdx.x;
    const int lane = t & 31;
    float sc = g_score[g * n + t];
    keys[t] = ((ull)__float_as_uint(sc) << 32) | (unsigned)t;
    inv[t] = -1;
    if (t < k) { sdeg[t] = 0.f; scnt[t] = 0; }
    if (t == 0) secnt = 0;
    __syncthreads();
    // bitonic sort, descending (scores in (0,1): float bits are order-preserving)
    for (int ks = 2; ks <= n; ks <<= 1) {
        for (int j = ks >> 1; j > 0; j >>= 1) {
            int ixj = t ^ j;
            if (ixj > t) {
                bool desc = ((t & ks) == 0);
                ull a = keys[t], b2 = keys[ixj];
                if ((a < b2) == desc) { keys[t] = b2; keys[ixj] = a; }
            }
            __syncthreads();
        }
    }
    if (t < k) {
        ull a = keys[t];
        int idx = (int)(a & 0xffffffffu);
        g_perm[g * k + t] = idx;
        g_vals[g * k + t] = __uint_as_float((unsigned)(a >> 32));
        inv[idx] = t;
    }
    __syncthreads();
    if (!do_remap) return;

    const int cin = fixedc ? fixedc : gcin[g];
    const int ibase = g * istride;
    const int obase = g * ostride;
    // warp-aggregated compaction: one shared atomic per warp, popc prefix
    for (int i0 = (t & ~31); i0 < cin; i0 += n) {
        int i = i0 + lane;
        int s = 0, d = 0, slid = -1, dlid = -1;
        float w = 0.f;
        bool valid = false;
        if (i < cin) {
            s = esi[ibase + i]; d = edi[ibase + i]; w = ewi[ibase + i];
            slid = inv[s - g * n]; dlid = inv[d - g * n];
            valid = (w != 0.f) && (slid >= 0) && (dlid >= 0);
        }
        unsigned bal = __ballot_sync(0xffffffffu, valid);
        int cntb = __popc(bal);
        int base = 0;
        if (lane == 0 && cntb) base = atomicAdd(&secnt, cntb);
        base = __shfl_sync(0xffffffffu, base, 0);
        if (valid) {
            int pos = base + __popc(bal & ((1u << lane) - 1u));
            if (pos < ostride) {
                eso[obase + pos] = g * k + slid;
                edo[obase + pos] = g * k + dlid;
                ewo[obase + pos] = w;
                atomicAdd(&sdeg[dlid], w);
            }
        }
    }
    __syncthreads();
    int cout = min(secnt, ostride);
    if (t == 0) gcout[g] = cout;
    // CSR fill with fused symmetric norm
    for (int i = t; i < cout; i += n) {
        int s = eso[obase + i], d = edo[obase + i];
        float w = ewo[obase + i];
        int slid = s - g * k, dlid = d - g * k;
        float nv = rsqrtf(sdeg[slid] + 1.f) * w * rsqrtf(sdeg[dlid] + 1.f);
        int pos = atomicAdd(&scnt[dlid], 1);
        if (pos < CSLOT) {
            g_csrc[(size_t)d * CSLOT + pos] = s;
            g_cnorm[(size_t)d * CSLOT + pos] = nv;
        }
    }
    __syncthreads();
    if (t < k) {
        g_deg[g * k + t] = sdeg[t];
        g_cnt[g * k + t] = min(scnt[t], CSLOT);
    }
}

// ---------------- readout (fused pool3 gather + gmp||gap + linear + sigmoid) --
__global__ void __launch_bounds__(128) k_readout(const float* __restrict__ h,
                                                 const float* __restrict__ Wo,
                                                 const float* __restrict__ bo,
                                                 float* __restrict__ out,
                                                 int n, int k) {
    __shared__ float red[128];
    int b = blockIdx.x, f = threadIdx.x;
    float mx = -3.0e38f, sm = 0.f;
    for (int nd = 0; nd < k; nd++) {
        int row = b * n + g_perm[b * k + nd];
        float v = h[row * FDIM + f] * g_vals[b * k + nd];
        v = fmaxf(v, 0.f);
        mx = fmaxf(mx, v);
        sm += v;
    }
    float mean = sm / (float)k;
    out[BNUM + b * 256 + f] = mx;            // cat block: [max | mean]
    out[BNUM + b * 256 + 128 + f] = mean;
    red[f] = mx * Wo[f] + mean * Wo[128 + f];
    __syncthreads();
    for (int s = 64; s > 0; s >>= 1) {
        if (f < s) red[f] += red[f + s];
        __syncthreads();
    }
    if (f == 0) {
        float o = red[0] + bo[0];
        out[b] = 1.f / (1.f + expf(-o));
    }
}

// ---------------- driver -------------------------------------------------------
extern "C" void kernel_launch(void* const* d_in, const int* in_sizes, int n_in,
                              void* d_out, int out_size) {
    const float* x  = (const float*)d_in[0];
    const int*   ei = (const int*)  d_in[1];
    const float* ew = (const float*)d_in[2];
    const float* W1 = (const float*)d_in[4];
    const float* b1 = (const float*)d_in[5];
    const float* p1 = (const float*)d_in[6];
    const float* W2 = (const float*)d_in[7];
    const float* b2 = (const float*)d_in[8];
    const float* p2 = (const float*)d_in[9];
    const float* W3 = (const float*)d_in[10];
    const float* b3 = (const float*)d_in[11];
    const float* p3 = (const float*)d_in[12];
    const float* Wo = (const float*)d_in[13];
    const float* bo = (const float*)d_in[14];
    float* out = (float*)d_out;

    float *P0, *P1;
    cudaGetSymbolAddress((void**)&P0, g_P0);
    cudaGetSymbolAddress((void**)&P1, g_P1);
    int *ES, *ED, *ESA, *EDA, *ESB, *EDB, *GCA, *GCB;
    float *EW, *EWA, *EWB;
    cudaGetSymbolAddress((void**)&ES, g_es);
    cudaGetSymbolAddress((void**)&ED, g_ed);
    cudaGetSymbolAddress((void**)&EW, g_ew);
    cudaGetSymbolAddress((void**)&ESA, g_esA);
    cudaGetSymbolAddress((void**)&EDA, g_edA);
    cudaGetSymbolAddress((void**)&EWA, g_ewA);
    cudaGetSymbolAddress((void**)&ESB, g_esB);
    cudaGetSymbolAddress((void**)&EDB, g_edB);
    cudaGetSymbolAddress((void**)&EWB, g_ewB);
    cudaGetSymbolAddress((void**)&GCA, g_gecA);
    cudaGetSymbolAddress((void**)&GCB, g_gecB);

    k_pnorm3<<<3, 128>>>(p1, p2, p3);
    k_edges<<<BNUM, 1024>>>(ei, ew);

    // ---- layer 1 (n=1024 -> k=512) ----
    k_gemm2<<<NT0 / 32, 128>>>(x, W1, P0);
    k_aggregate<<<NT0 / 8, 256>>>(P0, b1, p1, P1, NT0, 0);
    k_topk_rf<<<BNUM, 1024>>>(1024, 512,
                              ES, ED, EW, EPG0, (const int*)nullptr, EPG0,
                              ESA, EDA, EWA, ESTR1, GCA, 1);
    // ---- layer 2 (n=512 -> k=256) ----
    k_gemm2_g<<<(BNUM * 512) / 32, 128>>>(P1, W2, P0, 1024, 9);
    k_aggregate<<<(BNUM * 512) / 8, 256>>>(P0, b2, p2, P1, BNUM * 512, 1);
    k_topk_rf<<<BNUM, 512>>>(512, 256,
                             ESA, EDA, EWA, ESTR1, GCA, 0,
                             ESB, EDB, EWB, ESTR2, GCB, 1);
    // ---- layer 3 (n=256 -> k=128; sort only) ----
    k_gemm2_g<<<(BNUM * 256) / 32, 128>>>(P1, W3, P0, 512, 8);
    k_aggregate<<<(BNUM * 256) / 8, 256>>>(P0, b3, p3, P1, BNUM * 256, 2);
    k_topk_rf<<<BNUM, 256>>>(256, 128,
                             ESB, EDB, EWB, ESTR2, GCB, 0,
                             (int*)nullptr, (int*)nullptr, (float*)nullptr, 0,
                             (int*)nullptr, 0);

    k_readout<<<BNUM, 128>>>(P1, Wo, bo, out, 256, 128);
    (void)in_sizes; (void)n_in; (void)out_size;
}

// round 7
// speedup vs baseline: 1.0466x; 1.0466x over previous
#include <cuda_runtime.h>
#include <math.h>

// Problem constants (fixed by the reference)
#define BNUM 64
#define NPER 1024
#define FDIM 128
#define ETOT (BNUM * NPER * 16)   // 1,048,576 edges
#define NT0  (BNUM * NPER)        // 65,536 nodes at layer 1
#define EPG0 16384                // edges per graph, layer 0 (contiguous)
#define ESTR1 16384               // per-graph edge bound after pool1 (HARD bound)
#define ESTR2 16384               // per-graph edge bound after pool2 (HARD bound)
#define CSLOT 64                  // CSR slots per node (in-degree ~Poisson(16))

typedef unsigned long long ull;

// ---------------- scratch (device globals; no runtime allocation) ----------
__device__ float g_P0[(size_t)NT0 * FDIM];      // xW buffer
__device__ float g_P1[(size_t)NT0 * FDIM];      // conv output
__device__ float g_deg[NT0];
__device__ int   g_cnt[NT0];
__device__ float g_score[NT0];
__device__ int   g_perm[NT0];
__device__ float g_vals[NT0];
__device__ int   g_es[ETOT];                    // layer-0 edges (converted)
__device__ int   g_ed[ETOT];
__device__ float g_ew[ETOT];
__device__ int   g_esA[BNUM * ESTR1];           // compacted edges after pool1
__device__ int   g_edA[BNUM * ESTR1];
__device__ float g_ewA[BNUM * ESTR1];
__device__ int   g_esB[BNUM * ESTR2];           // compacted edges after pool2
__device__ int   g_edB[BNUM * ESTR2];
__device__ float g_ewB[BNUM * ESTR2];
__device__ int   g_gecA[BNUM];                  // per-graph live-edge counts
__device__ int   g_gecB[BNUM];
__device__ int2  g_csr[(size_t)NT0 * CSLOT];    // packed CSR: (src, norm-bits)
__device__ float g_pnorm[3];

__device__ __forceinline__ ull fma2(ull a, ull b, ull c) {
    ull d;
    asm("fma.rn.f32x2 %0, %1, %2, %3;" : "=l"(d) : "l"(a), "l"(b), "l"(c));
    return d;
}

// ---------------- ||p|| for the three pooling layers ------------------------
__global__ void k_pnorm3(const float* __restrict__ p1,
                         const float* __restrict__ p2,
                         const float* __restrict__ p3) {
    __shared__ float sh[FDIM];
    const float* p = (blockIdx.x == 0) ? p1 : (blockIdx.x == 1) ? p2 : p3;
    float v = p[threadIdx.x];
    sh[threadIdx.x] = v * v;
    __syncthreads();
    for (int s = 64; s > 0; s >>= 1) {
        if (threadIdx.x < s) sh[threadIdx.x] += sh[threadIdx.x + s];
        __syncthreads();
    }
    if (threadIdx.x == 0) g_pnorm[blockIdx.x] = sqrtf(sh[0]);
}

// ---------------- k_edges: block = graph -------------------------------------
// dtype probe + edge conversion + shared-mem degree + layer-1 CSR fill, fused.
__global__ void __launch_bounds__(1024) k_edges(const int* __restrict__ ei,
                                                const float* __restrict__ ew) {
    __shared__ float sdeg[NPER];
    __shared__ int   scnt[NPER];
    __shared__ int   s64;
    const int g = blockIdx.x, t = threadIdx.x;
    sdeg[t] = 0.f;
    scnt[t] = 0;
    if (t == 0) s64 = 1;
    __syncthreads();
    const int e0 = g * EPG0;
    // probe: for int64 edge ids (<2^31) all odd words are 0; for int32 they are
    // node ids (nonzero with overwhelming probability over 512 samples)
    if (t < 512 && ei[2 * (e0 + t) + 1] != 0) s64 = 0;
    __syncthreads();
    const int is64 = s64;
    int   ls[EPG0 / 1024], ld[EPG0 / 1024];
    float lw[EPG0 / 1024];
    #pragma unroll
    for (int j = 0; j < EPG0 / 1024; j++) {
        int e = e0 + t + j * 1024;
        int s, d;
        if (is64) { s = ei[2 * e]; d = ei[2 * (ETOT + e)]; }
        else      { s = ei[e];     d = ei[ETOT + e]; }
        float w = ew[e];
        ls[j] = s; ld[j] = d; lw[j] = w;
        g_es[e] = s; g_ed[e] = d; g_ew[e] = w;
        if (w != 0.f) atomicAdd(&sdeg[d - g * NPER], w);
    }
    __syncthreads();
    #pragma unroll
    for (int j = 0; j < EPG0 / 1024; j++) {
        float w = lw[j];
        if (w == 0.f) continue;
        int s = ls[j], d = ld[j];
        int sl = s - g * NPER, dl = d - g * NPER;
        float nv = rsqrtf(sdeg[sl] + 1.f) * w * rsqrtf(sdeg[dl] + 1.f);
        int pos = atomicAdd(&scnt[dl], 1);
        if (pos < CSLOT) {
            g_csr[(size_t)d * CSLOT + pos] = make_int2(s, __float_as_int(nv));
        }
    }
    __syncthreads();
    g_deg[g * NPER + t] = sdeg[t];
    g_cnt[g * NPER + t] = min(scnt[t], CSLOT);
}

// ---------------- GEMM (f32x2 packed): Y[NT,128] = X[NT,128] @ W[128,128] ----
__global__ void __launch_bounds__(128) k_gemm2(const float* __restrict__ X,
                                               const float* __restrict__ W,
                                               float* __restrict__ Y) {
    __shared__ float2 xs2[32][FDIM];
    const int row0 = blockIdx.x * 32;
    const int tid = threadIdx.x;
    const int tx = tid & 63, ty = tid >> 6;
    #pragma unroll
    for (int i = tid; i < 32 * FDIM; i += 128) {
        int r = i >> 7, k = i & 127;
        float v = X[(row0 + r) * FDIM + k];
        xs2[r][k] = make_float2(v, v);
    }
    __syncthreads();
    const ull* W2 = (const ull*)W;
    ull acc[16];
    #pragma unroll
    for (int r = 0; r < 16; r++) acc[r] = 0ull;
    const ull* xrow = (const ull*)&xs2[ty * 16][0];
    #pragma unroll 4
    for (int k = 0; k < FDIM; k++) {
        ull w2 = W2[k * 64 + tx];
        #pragma unroll
        for (int r = 0; r < 16; r++)
            acc[r] = fma2(xrow[r * FDIM + k], w2, acc[r]);
    }
    float2* Y2 = (float2*)Y;
    #pragma unroll
    for (int r = 0; r < 16; r++) {
        float2 res = *(float2*)&acc[r];
        Y2[(row0 + ty * 16 + r) * 64 + tx] = res;
    }
}

// Same GEMM with fused pool-gather: row m = relu(H[g*n + perm[m]] * vals[m]).
__global__ void __launch_bounds__(128) k_gemm2_g(const float* __restrict__ H,
                                                 const float* __restrict__ W,
                                                 float* __restrict__ Y,
                                                 int n, int kshift) {
    __shared__ float2 xs2[32][FDIM];
    const int row0 = blockIdx.x * 32;
    const int tid = threadIdx.x;
    const int tx = tid & 63, ty = tid >> 6;
    #pragma unroll
    for (int i = tid; i < 32 * FDIM; i += 128) {
        int r = i >> 7, k = i & 127;
        int m = row0 + r;
        int g = m >> kshift;
        int row = g * n + g_perm[m];
        float v = fmaxf(H[row * FDIM + k] * g_vals[m], 0.f);
        xs2[r][k] = make_float2(v, v);
    }
    __syncthreads();
    const ull* W2 = (const ull*)W;
    ull acc[16];
    #pragma unroll
    for (int r = 0; r < 16; r++) acc[r] = 0ull;
    const ull* xrow = (const ull*)&xs2[ty * 16][0];
    #pragma unroll 4
    for (int k = 0; k < FDIM; k++) {
        ull w2 = W2[k * 64 + tx];
        #pragma unroll
        for (int r = 0; r < 16; r++)
            acc[r] = fma2(xrow[r * FDIM + k], w2, acc[r]);
    }
    float2* Y2 = (float2*)Y;
    #pragma unroll
    for (int r = 0; r < 16; r++) {
        float2 res = *(float2*)&acc[r];
        Y2[(row0 + ty * 16 + r) * 64 + tx] = res;
    }
}

// ---------------- aggregate + fused topk score: warp per dst node ------------
// Per edge: one uniform-address LDG.64 of the packed CSR record (broadcast, 1
// wavefront, L1-resident) + one gathered LDG.128. No shuffles, no selects.
// unroll-4 gives 4 independent gather chains; dual accumulators split the FMA
// dependency chain.
__global__ void __launch_bounds__(256) k_aggregate(const float* __restrict__ xW,
                                                   const float* __restrict__ b,
                                                   const float* __restrict__ p,
                                                   float* __restrict__ out,
                                                   int nt, int layer) {
    int node = blockIdx.x * 8 + (threadIdx.x >> 5);
    int lane = threadIdx.x & 31;
    if (node >= nt) return;
    const float4* xw4 = (const float4*)xW;
    float4 bv = ((const float4*)b)[lane];
    float di = rsqrtf(g_deg[node] + 1.f);
    float sl = di * di;
    float4 sv = xw4[(size_t)node * 32 + lane];
    float4 acc, acc2;
    acc.x = sl * sv.x + bv.x;
    acc.y = sl * sv.y + bv.y;
    acc.z = sl * sv.z + bv.z;
    acc.w = sl * sv.w + bv.w;
    acc2.x = 0.f; acc2.y = 0.f; acc2.z = 0.f; acc2.w = 0.f;
    const int cnt = g_cnt[node];
    const int2* rec = &g_csr[(size_t)node * CSLOT];
    int j = 0;
    for (; j + 4 <= cnt; j += 4) {
        int2 r0 = rec[j + 0];               // uniform broadcast loads
        int2 r1 = rec[j + 1];
        int2 r2 = rec[j + 2];
        int2 r3 = rec[j + 3];
        float4 v0 = xw4[(size_t)r0.x * 32 + lane];   // 4 independent gathers
        float4 v1 = xw4[(size_t)r1.x * 32 + lane];
        float4 v2 = xw4[(size_t)r2.x * 32 + lane];
        float4 v3 = xw4[(size_t)r3.x * 32 + lane];
        float m0 = __int_as_float(r0.y);
        float m1 = __int_as_float(r1.y);
        float m2 = __int_as_float(r2.y);
        float m3 = __int_as_float(r3.y);
        acc.x  = fmaf(m0, v0.x, acc.x);  acc2.x = fmaf(m1, v1.x, acc2.x);
        acc.y  = fmaf(m0, v0.y, acc.y);  acc2.y = fmaf(m1, v1.y, acc2.y);
        acc.z  = fmaf(m0, v0.z, acc.z);  acc2.z = fmaf(m1, v1.z, acc2.z);
        acc.w  = fmaf(m0, v0.w, acc.w);  acc2.w = fmaf(m1, v1.w, acc2.w);
        acc.x  = fmaf(m2, v2.x, acc.x);  acc2.x = fmaf(m3, v3.x, acc2.x);
        acc.y  = fmaf(m2, v2.y, acc.y);  acc2.y = fmaf(m3, v3.y, acc2.y);
        acc.z  = fmaf(m2, v2.z, acc.z);  acc2.z = fmaf(m3, v3.z, acc2.z);
        acc.w  = fmaf(m2, v2.w, acc.w);  acc2.w = fmaf(m3, v3.w, acc2.w);
    }
    for (; j < cnt; j++) {
        int2 r0 = rec[j];
        float4 v = xw4[(size_t)r0.x * 32 + lane];
        float m = __int_as_float(r0.y);
        acc.x = fmaf(m, v.x, acc.x);
        acc.y = fmaf(m, v.y, acc.y);
        acc.z = fmaf(m, v.z, acc.z);
        acc.w = fmaf(m, v.w, acc.w);
    }
    acc.x += acc2.x; acc.y += acc2.y; acc.z += acc2.z; acc.w += acc2.w;
    ((float4*)out)[(size_t)node * 32 + lane] = acc;
    // fused topk score
    float4 pv = ((const float4*)p)[lane];
    float ds = acc.x * pv.x + acc.y * pv.y + acc.z * pv.z + acc.w * pv.w;
    #pragma unroll
    for (int o = 16; o > 0; o >>= 1) ds += __shfl_xor_sync(0xffffffffu, ds, o);
    if (lane == 0) {
        float sc = ds / g_pnorm[layer];
        g_score[node] = 1.f / (1.f + expf(-sc));
    }
}

// ---------------- topk + remap + compact + deg + CSR fill (block = graph) ----
__global__ void k_topk_rf(int n, int k,
                          const int* __restrict__ esi, const int* __restrict__ edi,
                          const float* __restrict__ ewi, int istride,
                          const int* __restrict__ gcin, int fixedc,
                          int* __restrict__ eso, int* __restrict__ edo,
                          float* __restrict__ ewo, int ostride,
                          int* __restrict__ gcout, int do_remap) {
    __shared__ ull   keys[1024];
    __shared__ int   inv[1024];
    __shared__ float sdeg[512];
    __shared__ int   scnt[512];
    __shared__ int   secnt;
    const int g = blockIdx.x, t = threadIdx.x;
    const int lane = t & 31;
    float sc = g_score[g * n + t];
    keys[t] = ((ull)__float_as_uint(sc) << 32) | (unsigned)t;
    inv[t] = -1;
    if (t < k) { sdeg[t] = 0.f; scnt[t] = 0; }
    if (t == 0) secnt = 0;
    __syncthreads();
    // bitonic sort, descending (scores in (0,1): float bits are order-preserving)
    for (int ks = 2; ks <= n; ks <<= 1) {
        for (int j = ks >> 1; j > 0; j >>= 1) {
            int ixj = t ^ j;
            if (ixj > t) {
                bool desc = ((t & ks) == 0);
                ull a = keys[t], b2 = keys[ixj];
                if ((a < b2) == desc) { keys[t] = b2; keys[ixj] = a; }
            }
            __syncthreads();
        }
    }
    if (t < k) {
        ull a = keys[t];
        int idx = (int)(a & 0xffffffffu);
        g_perm[g * k + t] = idx;
        g_vals[g * k + t] = __uint_as_float((unsigned)(a >> 32));
        inv[idx] = t;
    }
    __syncthreads();
    if (!do_remap) return;

    const int cin = fixedc ? fixedc : gcin[g];
    const int ibase = g * istride;
    const int obase = g * ostride;
    // warp-aggregated compaction: one shared atomic per warp, popc prefix
    for (int i0 = (t & ~31); i0 < cin; i0 += n) {
        int i = i0 + lane;
        int s = 0, d = 0, slid = -1, dlid = -1;
        float w = 0.f;
        bool valid = false;
        if (i < cin) {
            s = esi[ibase + i]; d = edi[ibase + i]; w = ewi[ibase + i];
            slid = inv[s - g * n]; dlid = inv[d - g * n];
            valid = (w != 0.f) && (slid >= 0) && (dlid >= 0);
        }
        unsigned bal = __ballot_sync(0xffffffffu, valid);
        int cntb = __popc(bal);
        int base = 0;
        if (lane == 0 && cntb) base = atomicAdd(&secnt, cntb);
        base = __shfl_sync(0xffffffffu, base, 0);
        if (valid) {
            int pos = base + __popc(bal & ((1u << lane) - 1u));
            if (pos < ostride) {
                eso[obase + pos] = g * k + slid;
                edo[obase + pos] = g * k + dlid;
                ewo[obase + pos] = w;
                atomicAdd(&sdeg[dlid], w);
            }
        }
    }
    __syncthreads();
    int cout = min(secnt, ostride);
    if (t == 0) gcout[g] = cout;
    // CSR fill with fused symmetric norm (packed int2 record, single STG.64)
    for (int i = t; i < cout; i += n) {
        int s = eso[obase + i], d = edo[obase + i];
        float w = ewo[obase + i];
        int slid = s - g * k, dlid = d - g * k;
        float nv = rsqrtf(sdeg[slid] + 1.f) * w * rsqrtf(sdeg[dlid] + 1.f);
        int pos = atomicAdd(&scnt[dlid], 1);
        if (pos < CSLOT) {
            g_csr[(size_t)d * CSLOT + pos] = make_int2(s, __float_as_int(nv));
        }
    }
    __syncthreads();
    if (t < k) {
        g_deg[g * k + t] = sdeg[t];
        g_cnt[g * k + t] = min(scnt[t], CSLOT);
    }
}

// ---------------- readout (fused pool3 gather + gmp||gap + linear + sigmoid) --
__global__ void __launch_bounds__(128) k_readout(const float* __restrict__ h,
                                                 const float* __restrict__ Wo,
                                                 const float* __restrict__ bo,
                                                 float* __restrict__ out,
                                                 int n, int k) {
    __shared__ float red[128];
    int b = blockIdx.x, f = threadIdx.x;
    float mx = -3.0e38f, sm = 0.f;
    for (int nd = 0; nd < k; nd++) {
        int row = b * n + g_perm[b * k + nd];
        float v = h[row * FDIM + f] * g_vals[b * k + nd];
        v = fmaxf(v, 0.f);
        mx = fmaxf(mx, v);
        sm += v;
    }
    float mean = sm / (float)k;
    out[BNUM + b * 256 + f] = mx;            // cat block: [max | mean]
    out[BNUM + b * 256 + 128 + f] = mean;
    red[f] = mx * Wo[f] + mean * Wo[128 + f];
    __syncthreads();
    for (int s = 64; s > 0; s >>= 1) {
        if (f < s) red[f] += red[f + s];
        __syncthreads();
    }
    if (f == 0) {
        float o = red[0] + bo[0];
        out[b] = 1.f / (1.f + expf(-o));
    }
}

// ---------------- driver -------------------------------------------------------
extern "C" void kernel_launch(void* const* d_in, const int* in_sizes, int n_in,
                              void* d_out, int out_size) {
    const float* x  = (const float*)d_in[0];
    const int*   ei = (const int*)  d_in[1];
    const float* ew = (const float*)d_in[2];
    const float* W1 = (const float*)d_in[4];
    const float* b1 = (const float*)d_in[5];
    const float* p1 = (const float*)d_in[6];
    const float* W2 = (const float*)d_in[7];
    const float* b2 = (const float*)d_in[8];
    const float* p2 = (const float*)d_in[9];
    const float* W3 = (const float*)d_in[10];
    const float* b3 = (const float*)d_in[11];
    const float* p3 = (const float*)d_in[12];
    const float* Wo = (const float*)d_in[13];
    const float* bo = (const float*)d_in[14];
    float* out = (float*)d_out;

    float *P0, *P1;
    cudaGetSymbolAddress((void**)&P0, g_P0);
    cudaGetSymbolAddress((void**)&P1, g_P1);
    int *ES, *ED, *ESA, *EDA, *ESB, *EDB, *GCA, *GCB;
    float *EW, *EWA, *EWB;
    cudaGetSymbolAddress((void**)&ES, g_es);
    cudaGetSymbolAddress((void**)&ED, g_ed);
    cudaGetSymbolAddress((void**)&EW, g_ew);
    cudaGetSymbolAddress((void**)&ESA, g_esA);
    cudaGetSymbolAddress((void**)&EDA, g_edA);
    cudaGetSymbolAddress((void**)&EWA, g_ewA);
    cudaGetSymbolAddress((void**)&ESB, g_esB);
    cudaGetSymbolAddress((void**)&EDB, g_edB);
    cudaGetSymbolAddress((void**)&EWB, g_ewB);
    cudaGetSymbolAddress((void**)&GCA, g_gecA);
    cudaGetSymbolAddress((void**)&GCB, g_gecB);

    k_pnorm3<<<3, 128>>>(p1, p2, p3);
    k_edges<<<BNUM, 1024>>>(ei, ew);

    // ---- layer 1 (n=1024 -> k=512) ----
    k_gemm2<<<NT0 / 32, 128>>>(x, W1, P0);
    k_aggregate<<<NT0 / 8, 256>>>(P0, b1, p1, P1, NT0, 0);
    k_topk_rf<<<BNUM, 1024>>>(1024, 512,
                              ES, ED, EW, EPG0, (const int*)nullptr, EPG0,
                              ESA, EDA, EWA, ESTR1, GCA, 1);
    // ---- layer 2 (n=512 -> k=256) ----
    k_gemm2_g<<<(BNUM * 512) / 32, 128>>>(P1, W2, P0, 1024, 9);
    k_aggregate<<<(BNUM * 512) / 8, 256>>>(P0, b2, p2, P1, BNUM * 512, 1);
    k_topk_rf<<<BNUM, 512>>>(512, 256,
                             ESA, EDA, EWA, ESTR1, GCA, 0,
                             ESB, EDB, EWB, ESTR2, GCB, 1);
    // ---- layer 3 (n=256 -> k=128; sort only) ----
    k_gemm2_g<<<(BNUM * 256) / 32, 128>>>(P1, W3, P0, 512, 8);
    k_aggregate<<<(BNUM * 256) / 8, 256>>>(P0, b3, p3, P1, BNUM * 256, 2);
    k_topk_rf<<<BNUM, 256>>>(256, 128,
                             ESB, EDB, EWB, ESTR2, GCB, 0,
                             (int*)nullptr, (int*)nullptr, (float*)nullptr, 0,
                             (int*)nullptr, 0);

    k_readout<<<BNUM, 128>>>(P1, Wo, bo, out, 256, 128);
    (void)in_sizes; (void)n_in; (void)out_size;
}

// round 8
// speedup vs baseline: 1.0774x; 1.0295x over previous
#include <cuda_runtime.h>
#include <math.h>

// Problem constants (fixed by the reference)
#define BNUM 64
#define NPER 1024
#define FDIM 128
#define ETOT (BNUM * NPER * 16)   // 1,048,576 edges
#define NT0  (BNUM * NPER)        // 65,536 nodes at layer 1
#define EPG0 16384                // edges per graph, layer 0 (contiguous)
#define ESTR1 16384               // per-graph edge bound after pool1 (HARD bound)
#define ESTR2 16384               // per-graph edge bound after pool2 (HARD bound)
#define CSLOT 64                  // CSR slots per node (in-degree ~Poisson(16))

typedef unsigned long long ull;

// ---------------- scratch (device globals; no runtime allocation) ----------
__device__ float g_P0[(size_t)NT0 * FDIM];      // xW buffer
__device__ float g_P1[(size_t)NT0 * FDIM];      // conv output
__device__ float g_deg[NT0];
__device__ int   g_cnt[NT0];
__device__ float g_score[NT0];
__device__ int   g_perm[NT0];
__device__ float g_vals[NT0];
__device__ int   g_es[ETOT];                    // layer-0 edges (converted)
__device__ int   g_ed[ETOT];
__device__ float g_ew[ETOT];
__device__ int   g_esA[BNUM * ESTR1];           // compacted edges after pool1
__device__ int   g_edA[BNUM * ESTR1];
__device__ float g_ewA[BNUM * ESTR1];
__device__ int   g_esB[BNUM * ESTR2];           // compacted edges after pool2
__device__ int   g_edB[BNUM * ESTR2];
__device__ float g_ewB[BNUM * ESTR2];
__device__ int   g_gecA[BNUM];                  // per-graph live-edge counts
__device__ int   g_gecB[BNUM];
__device__ int2  g_csr[(size_t)NT0 * CSLOT];    // packed CSR: (src, norm-bits)
__device__ float g_pnorm[3];

__device__ __forceinline__ ull fma2(ull a, ull b, ull c) {
    ull d;
    asm("fma.rn.f32x2 %0, %1, %2, %3;" : "=l"(d) : "l"(a), "l"(b), "l"(c));
    return d;
}

// ---------------- ||p|| for the three pooling layers ------------------------
__global__ void k_pnorm3(const float* __restrict__ p1,
                         const float* __restrict__ p2,
                         const float* __restrict__ p3) {
    __shared__ float sh[FDIM];
    const float* p = (blockIdx.x == 0) ? p1 : (blockIdx.x == 1) ? p2 : p3;
    float v = p[threadIdx.x];
    sh[threadIdx.x] = v * v;
    __syncthreads();
    for (int s = 64; s > 0; s >>= 1) {
        if (threadIdx.x < s) sh[threadIdx.x] += sh[threadIdx.x + s];
        __syncthreads();
    }
    if (threadIdx.x == 0) g_pnorm[blockIdx.x] = sqrtf(sh[0]);
}

// ---------------- k_edges: block = graph -------------------------------------
// dtype probe + edge conversion + shared-mem degree + layer-1 CSR fill, fused.
__global__ void __launch_bounds__(1024) k_edges(const int* __restrict__ ei,
                                                const float* __restrict__ ew) {
    __shared__ float sdeg[NPER];
    __shared__ int   scnt[NPER];
    __shared__ int   s64;
    const int g = blockIdx.x, t = threadIdx.x;
    sdeg[t] = 0.f;
    scnt[t] = 0;
    if (t == 0) s64 = 1;
    __syncthreads();
    const int e0 = g * EPG0;
    // probe: for int64 edge ids (<2^31) all odd words are 0; for int32 they are
    // node ids (nonzero with overwhelming probability over 512 samples)
    if (t < 512 && ei[2 * (e0 + t) + 1] != 0) s64 = 0;
    __syncthreads();
    const int is64 = s64;
    int   ls[EPG0 / 1024], ld[EPG0 / 1024];
    float lw[EPG0 / 1024];
    #pragma unroll
    for (int j = 0; j < EPG0 / 1024; j++) {
        int e = e0 + t + j * 1024;
        int s, d;
        if (is64) { s = ei[2 * e]; d = ei[2 * (ETOT + e)]; }
        else      { s = ei[e];     d = ei[ETOT + e]; }
        float w = ew[e];
        ls[j] = s; ld[j] = d; lw[j] = w;
        g_es[e] = s; g_ed[e] = d; g_ew[e] = w;
        if (w != 0.f) atomicAdd(&sdeg[d - g * NPER], w);
    }
    __syncthreads();
    #pragma unroll
    for (int j = 0; j < EPG0 / 1024; j++) {
        float w = lw[j];
        if (w == 0.f) continue;
        int s = ls[j], d = ld[j];
        int sl = s - g * NPER, dl = d - g * NPER;
        float nv = rsqrtf(sdeg[sl] + 1.f) * w * rsqrtf(sdeg[dl] + 1.f);
        int pos = atomicAdd(&scnt[dl], 1);
        if (pos < CSLOT) {
            g_csr[(size_t)d * CSLOT + pos] = make_int2(s, __float_as_int(nv));
        }
    }
    __syncthreads();
    g_deg[g * NPER + t] = sdeg[t];
    g_cnt[g * NPER + t] = min(scnt[t], CSLOT);
}

// ---------------- GEMM (f32x2 packed): Y[NT,128] = X[NT,128] @ W[128,128] ----
__global__ void __launch_bounds__(128) k_gemm2(const float* __restrict__ X,
                                               const float* __restrict__ W,
                                               float* __restrict__ Y) {
    __shared__ float2 xs2[32][FDIM];
    const int row0 = blockIdx.x * 32;
    const int tid = threadIdx.x;
    const int tx = tid & 63, ty = tid >> 6;
    #pragma unroll
    for (int i = tid; i < 32 * FDIM; i += 128) {
        int r = i >> 7, k = i & 127;
        float v = X[(row0 + r) * FDIM + k];
        xs2[r][k] = make_float2(v, v);
    }
    __syncthreads();
    const ull* W2 = (const ull*)W;
    ull acc[16];
    #pragma unroll
    for (int r = 0; r < 16; r++) acc[r] = 0ull;
    const ull* xrow = (const ull*)&xs2[ty * 16][0];
    #pragma unroll 4
    for (int k = 0; k < FDIM; k++) {
        ull w2 = W2[k * 64 + tx];
        #pragma unroll
        for (int r = 0; r < 16; r++)
            acc[r] = fma2(xrow[r * FDIM + k], w2, acc[r]);
    }
    float2* Y2 = (float2*)Y;
    #pragma unroll
    for (int r = 0; r < 16; r++) {
        float2 res = *(float2*)&acc[r];
        Y2[(row0 + ty * 16 + r) * 64 + tx] = res;
    }
}

// Same GEMM with fused pool-gather: row m = relu(H[g*n + perm[m]] * vals[m]).
__global__ void __launch_bounds__(128) k_gemm2_g(const float* __restrict__ H,
                                                 const float* __restrict__ W,
                                                 float* __restrict__ Y,
                                                 int n, int kshift) {
    __shared__ float2 xs2[32][FDIM];
    const int row0 = blockIdx.x * 32;
    const int tid = threadIdx.x;
    const int tx = tid & 63, ty = tid >> 6;
    #pragma unroll
    for (int i = tid; i < 32 * FDIM; i += 128) {
        int r = i >> 7, k = i & 127;
        int m = row0 + r;
        int g = m >> kshift;
        int row = g * n + g_perm[m];
        float v = fmaxf(H[row * FDIM + k] * g_vals[m], 0.f);
        xs2[r][k] = make_float2(v, v);
    }
    __syncthreads();
    const ull* W2 = (const ull*)W;
    ull acc[16];
    #pragma unroll
    for (int r = 0; r < 16; r++) acc[r] = 0ull;
    const ull* xrow = (const ull*)&xs2[ty * 16][0];
    #pragma unroll 4
    for (int k = 0; k < FDIM; k++) {
        ull w2 = W2[k * 64 + tx];
        #pragma unroll
        for (int r = 0; r < 16; r++)
            acc[r] = fma2(xrow[r * FDIM + k], w2, acc[r]);
    }
    float2* Y2 = (float2*)Y;
    #pragma unroll
    for (int r = 0; r < 16; r++) {
        float2 res = *(float2*)&acc[r];
        Y2[(row0 + ty * 16 + r) * 64 + tx] = res;
    }
}

// ---------------- aggregate + fused topk score: warp per dst node ------------
// Minimal-register form: per edge one uniform-address LDG.64 (packed record,
// broadcast) + one gathered LDG.128, single float4 accumulator. pragma unroll
// lets ptxas front-batch loads within the 42-reg budget; occupancy (48 warps)
// does the latency hiding.
__global__ void __launch_bounds__(256, 6) k_aggregate(const float* __restrict__ xW,
                                                      const float* __restrict__ b,
                                                      const float* __restrict__ p,
                                                      float* __restrict__ out,
                                                      int nt, int layer) {
    int node = blockIdx.x * 8 + (threadIdx.x >> 5);
    int lane = threadIdx.x & 31;
    if (node >= nt) return;
    const float4* xw4 = (const float4*)xW;
    float4 bv = ((const float4*)b)[lane];
    float di = rsqrtf(g_deg[node] + 1.f);
    float sl = di * di;
    float4 sv = xw4[(size_t)node * 32 + lane];
    float4 acc;
    acc.x = sl * sv.x + bv.x;
    acc.y = sl * sv.y + bv.y;
    acc.z = sl * sv.z + bv.z;
    acc.w = sl * sv.w + bv.w;
    const int cnt = g_cnt[node];
    const int2* rec = &g_csr[(size_t)node * CSLOT];
    #pragma unroll 4
    for (int j = 0; j < cnt; j++) {
        int2 r0 = rec[j];                          // uniform broadcast load
        float4 v = xw4[(size_t)r0.x * 32 + lane];  // gathered LDG.128
        float m = __int_as_float(r0.y);
        acc.x = fmaf(m, v.x, acc.x);
        acc.y = fmaf(m, v.y, acc.y);
        acc.z = fmaf(m, v.z, acc.z);
        acc.w = fmaf(m, v.w, acc.w);
    }
    ((float4*)out)[(size_t)node * 32 + lane] = acc;
    // fused topk score
    float4 pv = ((const float4*)p)[lane];
    float ds = acc.x * pv.x + acc.y * pv.y + acc.z * pv.z + acc.w * pv.w;
    #pragma unroll
    for (int o = 16; o > 0; o >>= 1) ds += __shfl_xor_sync(0xffffffffu, ds, o);
    if (lane == 0) {
        float sc = ds / g_pnorm[layer];
        g_score[node] = 1.f / (1.f + expf(-sc));
    }
}

// ---------------- topk + remap + compact + deg + CSR fill (block = graph) ----
__global__ void k_topk_rf(int n, int k,
                          const int* __restrict__ esi, const int* __restrict__ edi,
                          const float* __restrict__ ewi, int istride,
                          const int* __restrict__ gcin, int fixedc,
                          int* __restrict__ eso, int* __restrict__ edo,
                          float* __restrict__ ewo, int ostride,
                          int* __restrict__ gcout, int do_remap) {
    __shared__ ull   keys[1024];
    __shared__ int   inv[1024];
    __shared__ float sdeg[512];
    __shared__ int   scnt[512];
    __shared__ int   secnt;
    const int g = blockIdx.x, t = threadIdx.x;
    const int lane = t & 31;
    float sc = g_score[g * n + t];
    keys[t] = ((ull)__float_as_uint(sc) << 32) | (unsigned)t;
    inv[t] = -1;
    if (t < k) { sdeg[t] = 0.f; scnt[t] = 0; }
    if (t == 0) secnt = 0;
    __syncthreads();
    // bitonic sort, descending (scores in (0,1): float bits are order-preserving)
    for (int ks = 2; ks <= n; ks <<= 1) {
        for (int j = ks >> 1; j > 0; j >>= 1) {
            int ixj = t ^ j;
            if (ixj > t) {
                bool desc = ((t & ks) == 0);
                ull a = keys[t], b2 = keys[ixj];
                if ((a < b2) == desc) { keys[t] = b2; keys[ixj] = a; }
            }
            __syncthreads();
        }
    }
    if (t < k) {
        ull a = keys[t];
        int idx = (int)(a & 0xffffffffu);
        g_perm[g * k + t] = idx;
        g_vals[g * k + t] = __uint_as_float((unsigned)(a >> 32));
        inv[idx] = t;
    }
    __syncthreads();
    if (!do_remap) return;

    const int cin = fixedc ? fixedc : gcin[g];
    const int ibase = g * istride;
    const int obase = g * ostride;
    // warp-aggregated compaction: one shared atomic per warp, popc prefix
    for (int i0 = (t & ~31); i0 < cin; i0 += n) {
        int i = i0 + lane;
        int s = 0, d = 0, slid = -1, dlid = -1;
        float w = 0.f;
        bool valid = false;
        if (i < cin) {
            s = esi[ibase + i]; d = edi[ibase + i]; w = ewi[ibase + i];
            slid = inv[s - g * n]; dlid = inv[d - g * n];
            valid = (w != 0.f) && (slid >= 0) && (dlid >= 0);
        }
        unsigned bal = __ballot_sync(0xffffffffu, valid);
        int cntb = __popc(bal);
        int base = 0;
        if (lane == 0 && cntb) base = atomicAdd(&secnt, cntb);
        base = __shfl_sync(0xffffffffu, base, 0);
        if (valid) {
            int pos = base + __popc(bal & ((1u << lane) - 1u));
            if (pos < ostride) {
                eso[obase + pos] = g * k + slid;
                edo[obase + pos] = g * k + dlid;
                ewo[obase + pos] = w;
                atomicAdd(&sdeg[dlid], w);
            }
        }
    }
    __syncthreads();
    int cout = min(secnt, ostride);
    if (t == 0) gcout[g] = cout;
    // CSR fill with fused symmetric norm (packed int2 record, single STG.64)
    for (int i = t; i < cout; i += n) {
        int s = eso[obase + i], d = edo[obase + i];
        float w = ewo[obase + i];
        int slid = s - g * k, dlid = d - g * k;
        float nv = rsqrtf(sdeg[slid] + 1.f) * w * rsqrtf(sdeg[dlid] + 1.f);
        int pos = atomicAdd(&scnt[dlid], 1);
        if (pos < CSLOT) {
            g_csr[(size_t)d * CSLOT + pos] = make_int2(s, __float_as_int(nv));
        }
    }
    __syncthreads();
    if (t < k) {
        g_deg[g * k + t] = sdeg[t];
        g_cnt[g * k + t] = min(scnt[t], CSLOT);
    }
}

// ---------------- readout (fused pool3 gather + gmp||gap + linear + sigmoid) --
__global__ void __launch_bounds__(128) k_readout(const float* __restrict__ h,
                                                 const float* __restrict__ Wo,
                                                 const float* __restrict__ bo,
                                                 float* __restrict__ out,
                                                 int n, int k) {
    __shared__ float red[128];
    int b = blockIdx.x, f = threadIdx.x;
    float mx = -3.0e38f, sm = 0.f;
    for (int nd = 0; nd < k; nd++) {
        int row = b * n + g_perm[b * k + nd];
        float v = h[row * FDIM + f] * g_vals[b * k + nd];
        v = fmaxf(v, 0.f);
        mx = fmaxf(mx, v);
        sm += v;
    }
    float mean = sm / (float)k;
    out[BNUM + b * 256 + f] = mx;            // cat block: [max | mean]
    out[BNUM + b * 256 + 128 + f] = mean;
    red[f] = mx * Wo[f] + mean * Wo[128 + f];
    __syncthreads();
    for (int s = 64; s > 0; s >>= 1) {
        if (f < s) red[f] += red[f + s];
        __syncthreads();
    }
    if (f == 0) {
        float o = red[0] + bo[0];
        out[b] = 1.f / (1.f + expf(-o));
    }
}

// ---------------- driver -------------------------------------------------------
extern "C" void kernel_launch(void* const* d_in, const int* in_sizes, int n_in,
                              void* d_out, int out_size) {
    const float* x  = (const float*)d_in[0];
    const int*   ei = (const int*)  d_in[1];
    const float* ew = (const float*)d_in[2];
    const float* W1 = (const float*)d_in[4];
    const float* b1 = (const float*)d_in[5];
    const float* p1 = (const float*)d_in[6];
    const float* W2 = (const float*)d_in[7];
    const float* b2 = (const float*)d_in[8];
    const float* p2 = (const float*)d_in[9];
    const float* W3 = (const float*)d_in[10];
    const float* b3 = (const float*)d_in[11];
    const float* p3 = (const float*)d_in[12];
    const float* Wo = (const float*)d_in[13];
    const float* bo = (const float*)d_in[14];
    float* out = (float*)d_out;

    float *P0, *P1;
    cudaGetSymbolAddress((void**)&P0, g_P0);
    cudaGetSymbolAddress((void**)&P1, g_P1);
    int *ES, *ED, *ESA, *EDA, *ESB, *EDB, *GCA, *GCB;
    float *EW, *EWA, *EWB;
    cudaGetSymbolAddress((void**)&ES, g_es);
    cudaGetSymbolAddress((void**)&ED, g_ed);
    cudaGetSymbolAddress((void**)&EW, g_ew);
    cudaGetSymbolAddress((void**)&ESA, g_esA);
    cudaGetSymbolAddress((void**)&EDA, g_edA);
    cudaGetSymbolAddress((void**)&EWA, g_ewA);
    cudaGetSymbolAddress((void**)&ESB, g_esB);
    cudaGetSymbolAddress((void**)&EDB, g_edB);
    cudaGetSymbolAddress((void**)&EWB, g_ewB);
    cudaGetSymbolAddress((void**)&GCA, g_gecA);
    cudaGetSymbolAddress((void**)&GCB, g_gecB);

    k_pnorm3<<<3, 128>>>(p1, p2, p3);
    k_edges<<<BNUM, 1024>>>(ei, ew);

    // ---- layer 1 (n=1024 -> k=512) ----
    k_gemm2<<<NT0 / 32, 128>>>(x, W1, P0);
    k_aggregate<<<NT0 / 8, 256>>>(P0, b1, p1, P1, NT0, 0);
    k_topk_rf<<<BNUM, 1024>>>(1024, 512,
                              ES, ED, EW, EPG0, (const int*)nullptr, EPG0,
                              ESA, EDA, EWA, ESTR1, GCA, 1);
    // ---- layer 2 (n=512 -> k=256) ----
    k_gemm2_g<<<(BNUM * 512) / 32, 128>>>(P1, W2, P0, 1024, 9);
    k_aggregate<<<(BNUM * 512) / 8, 256>>>(P0, b2, p2, P1, BNUM * 512, 1);
    k_topk_rf<<<BNUM, 512>>>(512, 256,
                             ESA, EDA, EWA, ESTR1, GCA, 0,
                             ESB, EDB, EWB, ESTR2, GCB, 1);
    // ---- layer 3 (n=256 -> k=128; sort only) ----
    k_gemm2_g<<<(BNUM * 256) / 32, 128>>>(P1, W3, P0, 512, 8);
    k_aggregate<<<(BNUM * 256) / 8, 256>>>(P0, b3, p3, P1, BNUM * 256, 2);
    k_topk_rf<<<BNUM, 256>>>(256, 128,
                             ESB, EDB, EWB, ESTR2, GCB, 0,
                             (int*)nullptr, (int*)nullptr, (float*)nullptr, 0,
                             (int*)nullptr, 0);

    k_readout<<<BNUM, 128>>>(P1, Wo, bo, out, 256, 128);
    (void)in_sizes; (void)n_in; (void)out_size;
}

// round 9
// speedup vs baseline: 1.0992x; 1.0202x over previous
#include <cuda_runtime.h>
#include <math.h>

// Problem constants (fixed by the reference)
#define BNUM 64
#define NPER 1024
#define FDIM 128
#define ETOT (BNUM * NPER * 16)   // 1,048,576 edges
#define NT0  (BNUM * NPER)        // 65,536 nodes at layer 1
#define EPG0 16384                // edges per graph, layer 0 (contiguous)
#define ESTR1 16384               // per-graph edge bound after pool1 (HARD bound)
#define ESTR2 16384               // per-graph edge bound after pool2 (HARD bound)
#define CSLOT 64                  // CSR slots per node (in-degree ~Poisson(16))

typedef unsigned long long ull;

// ---------------- scratch (device globals; no runtime allocation) ----------
__device__ float g_P0[(size_t)NT0 * FDIM];      // xW buffer
__device__ float g_P1[(size_t)NT0 * FDIM];      // conv output
__device__ float g_deg[NT0];
__device__ int   g_cnt[NT0];
__device__ float g_score[NT0];
__device__ int   g_perm[NT0];
__device__ float g_vals[NT0];
__device__ int2  g_e2[ETOT];                    // layer-0 edges (src,dst) packed
__device__ float g_ew[ETOT];
__device__ int2  g_e2A[BNUM * ESTR1];           // compacted edges after pool1
__device__ float g_ewA[BNUM * ESTR1];
__device__ int2  g_e2B[BNUM * ESTR2];           // compacted edges after pool2
__device__ float g_ewB[BNUM * ESTR2];
__device__ int   g_gecA[BNUM];                  // per-graph live-edge counts
__device__ int   g_gecB[BNUM];
__device__ __align__(16) int2 g_csr[(size_t)NT0 * CSLOT]; // packed CSR (src, norm)
__device__ float g_pnorm[3];

__device__ __forceinline__ ull fma2(ull a, ull b, ull c) {
    ull d;
    asm("fma.rn.f32x2 %0, %1, %2, %3;" : "=l"(d) : "l"(a), "l"(b), "l"(c));
    return d;
}

// ---------------- k_edges: block = graph -------------------------------------
// pnorm (blocks 0-2) + dtype probe + edge conversion + shared-mem degree +
// layer-1 CSR fill, all fused.
__global__ void __launch_bounds__(1024) k_edges(const int* __restrict__ ei,
                                                const float* __restrict__ ew,
                                                const float* __restrict__ p1,
                                                const float* __restrict__ p2,
                                                const float* __restrict__ p3) {
    __shared__ float sdeg[NPER];
    __shared__ int   scnt[NPER];
    __shared__ int   s64;
    const int g = blockIdx.x, t = threadIdx.x;
    // fused ||p|| for the three pooling layers (blocks 0-2)
    if (g < 3) {
        const float* p = (g == 0) ? p1 : (g == 1) ? p2 : p3;
        if (t < 128) sdeg[t] = p[t] * p[t];
        __syncthreads();
        if (t == 0) {
            float s = 0.f;
            for (int i = 0; i < 128; i++) s += sdeg[i];
            g_pnorm[g] = sqrtf(s);
        }
        __syncthreads();
    }
    sdeg[t] = 0.f;
    scnt[t] = 0;
    if (t == 0) s64 = 1;
    __syncthreads();
    const int e0 = g * EPG0;
    // probe: for int64 edge ids (<2^31) all odd words are 0; for int32 they are
    // node ids (nonzero with overwhelming probability over 512 samples)
    if (t < 512 && ei[2 * (e0 + t) + 1] != 0) s64 = 0;
    __syncthreads();
    const int is64 = s64;
    int   ls[EPG0 / 1024], ld[EPG0 / 1024];
    float lw[EPG0 / 1024];
    #pragma unroll
    for (int j = 0; j < EPG0 / 1024; j++) {
        int e = e0 + t + j * 1024;
        int s, d;
        if (is64) { s = ei[2 * e]; d = ei[2 * (ETOT + e)]; }
        else      { s = ei[e];     d = ei[ETOT + e]; }
        float w = ew[e];
        ls[j] = s; ld[j] = d; lw[j] = w;
        g_e2[e] = make_int2(s, d);
        g_ew[e] = w;
        if (w != 0.f) atomicAdd(&sdeg[d - g * NPER], w);
    }
    __syncthreads();
    #pragma unroll
    for (int j = 0; j < EPG0 / 1024; j++) {
        float w = lw[j];
        if (w == 0.f) continue;
        int s = ls[j], d = ld[j];
        int sl = s - g * NPER, dl = d - g * NPER;
        float nv = rsqrtf(sdeg[sl] + 1.f) * w * rsqrtf(sdeg[dl] + 1.f);
        int pos = atomicAdd(&scnt[dl], 1);
        if (pos < CSLOT) {
            g_csr[(size_t)d * CSLOT + pos] = make_int2(s, __float_as_int(nv));
        }
    }
    __syncthreads();
    g_deg[g * NPER + t] = sdeg[t];
    g_cnt[g * NPER + t] = min(scnt[t], CSLOT);
}

// ---------------- GEMM (f32x2 packed): Y[NT,128] = X[NT,128] @ W[128,128] ----
__global__ void __launch_bounds__(128) k_gemm2(const float* __restrict__ X,
                                               const float* __restrict__ W,
                                               float* __restrict__ Y) {
    __shared__ float2 xs2[32][FDIM];
    const int row0 = blockIdx.x * 32;
    const int tid = threadIdx.x;
    const int tx = tid & 63, ty = tid >> 6;
    #pragma unroll
    for (int i = tid; i < 32 * FDIM; i += 128) {
        int r = i >> 7, k = i & 127;
        float v = X[(row0 + r) * FDIM + k];
        xs2[r][k] = make_float2(v, v);
    }
    __syncthreads();
    const ull* W2 = (const ull*)W;
    ull acc[16];
    #pragma unroll
    for (int r = 0; r < 16; r++) acc[r] = 0ull;
    const ull* xrow = (const ull*)&xs2[ty * 16][0];
    #pragma unroll 4
    for (int k = 0; k < FDIM; k++) {
        ull w2 = W2[k * 64 + tx];
        #pragma unroll
        for (int r = 0; r < 16; r++)
            acc[r] = fma2(xrow[r * FDIM + k], w2, acc[r]);
    }
    float2* Y2 = (float2*)Y;
    #pragma unroll
    for (int r = 0; r < 16; r++) {
        float2 res = *(float2*)&acc[r];
        Y2[(row0 + ty * 16 + r) * 64 + tx] = res;
    }
}

// Same GEMM with fused pool-gather: row m = relu(H[g*n + perm[m]] * vals[m]).
__global__ void __launch_bounds__(128) k_gemm2_g(const float* __restrict__ H,
                                                 const float* __restrict__ W,
                                                 float* __restrict__ Y,
                                                 int n, int kshift) {
    __shared__ float2 xs2[32][FDIM];
    const int row0 = blockIdx.x * 32;
    const int tid = threadIdx.x;
    const int tx = tid & 63, ty = tid >> 6;
    #pragma unroll
    for (int i = tid; i < 32 * FDIM; i += 128) {
        int r = i >> 7, k = i & 127;
        int m = row0 + r;
        int g = m >> kshift;
        int row = g * n + g_perm[m];
        float v = fmaxf(H[row * FDIM + k] * g_vals[m], 0.f);
        xs2[r][k] = make_float2(v, v);
    }
    __syncthreads();
    const ull* W2 = (const ull*)W;
    ull acc[16];
    #pragma unroll
    for (int r = 0; r < 16; r++) acc[r] = 0ull;
    const ull* xrow = (const ull*)&xs2[ty * 16][0];
    #pragma unroll 4
    for (int k = 0; k < FDIM; k++) {
        ull w2 = W2[k * 64 + tx];
        #pragma unroll
        for (int r = 0; r < 16; r++)
            acc[r] = fma2(xrow[r * FDIM + k], w2, acc[r]);
    }
    float2* Y2 = (float2*)Y;
    #pragma unroll
    for (int r = 0; r < 16; r++) {
        float2 res = *(float2*)&acc[r];
        Y2[(row0 + ty * 16 + r) * 64 + tx] = res;
    }
}

// ---------------- aggregate + fused topk score: warp per dst node ------------
// The block's 8-node CSR slab (512 int2 = 4KB) is staged into shared with 256
// coalesced LDG.128 (8 warp-issues) replacing ~128 serialized uniform LDG.64;
// the edge loop then reads records via broadcast LDS.64. Single float4
// accumulator keeps regs low; occupancy hides the gather latency.
__global__ void __launch_bounds__(256, 6) k_aggregate(const float* __restrict__ xW,
                                                      const float* __restrict__ b,
                                                      const float* __restrict__ p,
                                                      float* __restrict__ out,
                                                      int nt, int layer) {
    __shared__ int2 srec[8 * CSLOT];    // 4KB CSR slab for this block's 8 nodes
    const int w = threadIdx.x >> 5;
    const int lane = threadIdx.x & 31;
    const int node = blockIdx.x * 8 + w;
    // stage slab (grid is exactly nt/8 blocks; nt % 8 == 0 always)
    ((int4*)srec)[threadIdx.x] =
        ((const int4*)(g_csr + (size_t)blockIdx.x * (8 * CSLOT)))[threadIdx.x];
    __syncthreads();
    const float4* xw4 = (const float4*)xW;
    float4 bv = ((const float4*)b)[lane];
    float di = rsqrtf(g_deg[node] + 1.f);
    float sl = di * di;
    float4 sv = xw4[(size_t)node * 32 + lane];
    float4 acc;
    acc.x = sl * sv.x + bv.x;
    acc.y = sl * sv.y + bv.y;
    acc.z = sl * sv.z + bv.z;
    acc.w = sl * sv.w + bv.w;
    const int cnt = g_cnt[node];
    const int2* rec = &srec[w * CSLOT];
    #pragma unroll 4
    for (int j = 0; j < cnt; j++) {
        int2 r0 = rec[j];                          // broadcast LDS.64
        float4 v = xw4[(size_t)r0.x * 32 + lane];  // gathered LDG.128
        float m = __int_as_float(r0.y);
        acc.x = fmaf(m, v.x, acc.x);
        acc.y = fmaf(m, v.y, acc.y);
        acc.z = fmaf(m, v.z, acc.z);
        acc.w = fmaf(m, v.w, acc.w);
    }
    ((float4*)out)[(size_t)node * 32 + lane] = acc;
    // fused topk score
    float4 pv = ((const float4*)p)[lane];
    float ds = acc.x * pv.x + acc.y * pv.y + acc.z * pv.z + acc.w * pv.w;
    #pragma unroll
    for (int o = 16; o > 0; o >>= 1) ds += __shfl_xor_sync(0xffffffffu, ds, o);
    if (lane == 0) {
        float sc = ds / g_pnorm[layer];
        g_score[node] = 1.f / (1.f + expf(-sc));
    }
    (void)nt;
}

// ---------------- topk + remap + compact + deg + CSR fill (+readout) ---------
// block = graph. Layer 3 additionally runs the fused readout
// (pool3 gather + gmp||gap + linear + sigmoid) instead of the remap phase.
__global__ void k_topk_rf(int n, int k,
                          const int2* __restrict__ e2i, const float* __restrict__ ewi,
                          int istride, const int* __restrict__ gcin, int fixedc,
                          int2* __restrict__ e2o, float* __restrict__ ewo,
                          int ostride, int* __restrict__ gcout, int do_remap,
                          const float* __restrict__ h, const float* __restrict__ Wo,
                          const float* __restrict__ bo, float* __restrict__ out) {
    __shared__ ull   keys[1024];
    __shared__ int   inv[1024];
    __shared__ float sdeg[512];
    __shared__ int   scnt[512];
    __shared__ int   sperm[512];
    __shared__ float svals[512];
    __shared__ int   secnt;
    const int g = blockIdx.x, t = threadIdx.x;
    const int lane = t & 31;
    float sc = g_score[g * n + t];
    keys[t] = ((ull)__float_as_uint(sc) << 32) | (unsigned)t;
    inv[t] = -1;
    if (t < k) { sdeg[t] = 0.f; scnt[t] = 0; }
    if (t == 0) secnt = 0;
    __syncthreads();
    // bitonic sort, descending (scores in (0,1): float bits are order-preserving)
    for (int ks = 2; ks <= n; ks <<= 1) {
        for (int j = ks >> 1; j > 0; j >>= 1) {
            int ixj = t ^ j;
            if (ixj > t) {
                bool desc = ((t & ks) == 0);
                ull a = keys[t], b2 = keys[ixj];
                if ((a < b2) == desc) { keys[t] = b2; keys[ixj] = a; }
            }
            __syncthreads();
        }
    }
    if (t < k) {
        ull a = keys[t];
        int idx = (int)(a & 0xffffffffu);
        float val = __uint_as_float((unsigned)(a >> 32));
        g_perm[g * k + t] = idx;
        g_vals[g * k + t] = val;
        sperm[t] = idx;
        svals[t] = val;
        inv[idx] = t;
    }
    __syncthreads();

    if (do_remap) {
        const int cin = fixedc ? fixedc : gcin[g];
        const int ibase = g * istride;
        const int obase = g * ostride;
        // warp-aggregated compaction: one shared atomic per warp, popc prefix
        for (int i0 = (t & ~31); i0 < cin; i0 += n) {
            int i = i0 + lane;
            int slid = -1, dlid = -1;
            float w = 0.f;
            bool valid = false;
            if (i < cin) {
                int2 sd = e2i[ibase + i];
                w = ewi[ibase + i];
                slid = inv[sd.x - g * n]; dlid = inv[sd.y - g * n];
                valid = (w != 0.f) && (slid >= 0) && (dlid >= 0);
            }
            unsigned bal = __ballot_sync(0xffffffffu, valid);
            int cntb = __popc(bal);
            int base = 0;
            if (lane == 0 && cntb) base = atomicAdd(&secnt, cntb);
            base = __shfl_sync(0xffffffffu, base, 0);
            if (valid) {
                int pos = base + __popc(bal & ((1u << lane) - 1u));
                if (pos < ostride) {
                    e2o[obase + pos] = make_int2(g * k + slid, g * k + dlid);
                    ewo[obase + pos] = w;
                    atomicAdd(&sdeg[dlid], w);
                }
            }
        }
        __syncthreads();
        int cout = min(secnt, ostride);
        if (t == 0) gcout[g] = cout;
        // CSR fill with fused symmetric norm (packed int2 record, single STG.64)
        for (int i = t; i < cout; i += n) {
            int2 sd = e2o[obase + i];
            float w = ewo[obase + i];
            int slid = sd.x - g * k, dlid = sd.y - g * k;
            float nv = rsqrtf(sdeg[slid] + 1.f) * w * rsqrtf(sdeg[dlid] + 1.f);
            int pos = atomicAdd(&scnt[dlid], 1);
            if (pos < CSLOT) {
                g_csr[(size_t)sd.y * CSLOT + pos] = make_int2(sd.x, __float_as_int(nv));
            }
        }
        __syncthreads();
        if (t < k) {
            g_deg[g * k + t] = sdeg[t];
            g_cnt[g * k + t] = min(scnt[t], CSLOT);
        }
    } else {
        // fused readout: gmp||gap over the k kept nodes, then sigmoid(cat@Wo+bo)
        float red_contrib = 0.f;
        if (t < 128) {
            int f = t;
            float mx = -3.0e38f, sm = 0.f;
            for (int nd = 0; nd < k; nd++) {
                int row = g * n + sperm[nd];
                float v = h[row * FDIM + f] * svals[nd];
                v = fmaxf(v, 0.f);
                mx = fmaxf(mx, v);
                sm += v;
            }
            float mean = sm / (float)k;
            out[BNUM + g * 256 + f] = mx;            // cat block: [max | mean]
            out[BNUM + g * 256 + 128 + f] = mean;
            red_contrib = mx * Wo[f] + mean * Wo[128 + f];
        }
        // reduce via sdeg (free at this point)
        if (t < 128) sdeg[t] = red_contrib;
        __syncthreads();
        for (int s = 64; s > 0; s >>= 1) {
            if (t < s) sdeg[t] += sdeg[t + s];
            __syncthreads();
        }
        if (t == 0) {
            float o = sdeg[0] + bo[0];
            out[g] = 1.f / (1.f + expf(-o));
        }
    }
}

// ---------------- driver -------------------------------------------------------
extern "C" void kernel_launch(void* const* d_in, const int* in_sizes, int n_in,
                              void* d_out, int out_size) {
    const float* x  = (const float*)d_in[0];
    const int*   ei = (const int*)  d_in[1];
    const float* ew = (const float*)d_in[2];
    const float* W1 = (const float*)d_in[4];
    const float* b1 = (const float*)d_in[5];
    const float* p1 = (const float*)d_in[6];
    const float* W2 = (const float*)d_in[7];
    const float* b2 = (const float*)d_in[8];
    const float* p2 = (const float*)d_in[9];
    const float* W3 = (const float*)d_in[10];
    const float* b3 = (const float*)d_in[11];
    const float* p3 = (const float*)d_in[12];
    const float* Wo = (const float*)d_in[13];
    const float* bo = (const float*)d_in[14];
    float* out = (float*)d_out;

    float *P0, *P1;
    cudaGetSymbolAddress((void**)&P0, g_P0);
    cudaGetSymbolAddress((void**)&P1, g_P1);
    int2 *E2, *E2A, *E2B;
    int *GCA, *GCB;
    float *EW, *EWA, *EWB;
    cudaGetSymbolAddress((void**)&E2, g_e2);
    cudaGetSymbolAddress((void**)&EW, g_ew);
    cudaGetSymbolAddress((void**)&E2A, g_e2A);
    cudaGetSymbolAddress((void**)&EWA, g_ewA);
    cudaGetSymbolAddress((void**)&E2B, g_e2B);
    cudaGetSymbolAddress((void**)&EWB, g_ewB);
    cudaGetSymbolAddress((void**)&GCA, g_gecA);
    cudaGetSymbolAddress((void**)&GCB, g_gecB);

    k_edges<<<BNUM, 1024>>>(ei, ew, p1, p2, p3);

    // ---- layer 1 (n=1024 -> k=512) ----
    k_gemm2<<<NT0 / 32, 128>>>(x, W1, P0);
    k_aggregate<<<NT0 / 8, 256>>>(P0, b1, p1, P1, NT0, 0);
    k_topk_rf<<<BNUM, 1024>>>(1024, 512,
                              E2, EW, EPG0, (const int*)nullptr, EPG0,
                              E2A, EWA, ESTR1, GCA, 1,
                              (const float*)nullptr, (const float*)nullptr,
                              (const float*)nullptr, (float*)nullptr);
    // ---- layer 2 (n=512 -> k=256) ----
    k_gemm2_g<<<(BNUM * 512) / 32, 128>>>(P1, W2, P0, 1024, 9);
    k_aggregate<<<(BNUM * 512) / 8, 256>>>(P0, b2, p2, P1, BNUM * 512, 1);
    k_topk_rf<<<BNUM, 512>>>(512, 256,
                             E2A, EWA, ESTR1, GCA, 0,
                             E2B, EWB, ESTR2, GCB, 1,
                             (const float*)nullptr, (const float*)nullptr,
                             (const float*)nullptr, (float*)nullptr);
    // ---- layer 3 (n=256 -> k=128; sort + fused readout) ----
    k_gemm2_g<<<(BNUM * 256) / 32, 128>>>(P1, W3, P0, 512, 8);
    k_aggregate<<<(BNUM * 256) / 8, 256>>>(P0, b3, p3, P1, BNUM * 256, 2);
    k_topk_rf<<<BNUM, 256>>>(256, 128,
                             E2B, EWB, ESTR2, GCB, 0,
                             (int2*)nullptr, (float*)nullptr, 0,
                             (int*)nullptr, 0,
                             P1, Wo, bo, out);

    (void)in_sizes; (void)n_in; (void)out_size;
}